// round 3
// baseline (speedup 1.0000x reference)
#include <cuda_runtime.h>

// Problem constants
#define NB_UP    8      // electrons per spin channel
#define NMO_     40     // molecular orbitals
#define NELEC_   16     // total electrons (2 * NB_UP)
#define COL_STRIDE 12   // floats per stored column (48 B): makes the 8 residues
                        // of (col*12 mod 32) pairwise-disjoint 4-bank ranges

// One block per walker, one thread per CI configuration.
// Shared layout is COLUMN-MAJOR: mo_T[(s*NMO_+col)*COL_STRIDE + i] = mo[b, s*8+i, col]
// so a Slater-matrix column gather is two LDS.128 instead of eight LDS.32.
__global__ __launch_bounds__(256, 3)
void slater_det_kernel(const float* __restrict__ mo,
                       const int*   __restrict__ cup,
                       const int*   __restrict__ cdown,
                       float*       __restrict__ out,
                       int nconf)
{
    __shared__ float mo_T[2 * NMO_ * COL_STRIDE];   // 960 floats = 3840 B

    const int b = blockIdx.x;
    const int t = threadIdx.x;

    // Stage + transpose this walker's MO block (16x40 f32, 640 elements).
    // Global reads are warp-coalesced; scattered STS writes are cheap.
    {
        const float* src = mo + (size_t)b * (NELEC_ * NMO_);
        #pragma unroll
        for (int idx = t; idx < NELEC_ * NMO_; idx += 256) {
            const int i   = idx / NMO_;     // electron row 0..15
            const int col = idx % NMO_;     // MO column 0..39
            const int s   = i >> 3;
            const int ii  = i & 7;
            mo_T[(s * NMO_ + col) * COL_STRIDE + ii] = src[idx];
        }
    }
    __syncthreads();

    const int c = t;
    if (c >= nconf) return;

    float result = 1.0f;

    #pragma unroll 1   // one code copy for both spins (I$ footprint)
    for (int s = 0; s < 2; ++s) {
        const int*   cw      = ((s == 0) ? cup : cdown) + c * NB_UP;
        const float* colbase = mo_T + s * NMO_ * COL_STRIDE;

        // Vectorized index load: 8 ints = 2x int4 (row base is 32B-aligned).
        const int4 ci0 = __ldg((const int4*)cw);
        const int4 ci1 = __ldg((const int4*)cw + 1);
        int cols[NB_UP] = {ci0.x, ci0.y, ci0.z, ci0.w, ci1.x, ci1.y, ci1.z, ci1.w};

        // Gather the 8x8 Slater matrix: column j = mo column cols[j],
        // contiguous 8 floats -> two LDS.128 per column.
        float a[NB_UP][NB_UP];
        #pragma unroll
        for (int j = 0; j < NB_UP; ++j) {
            const float4* p = reinterpret_cast<const float4*>(colbase + cols[j] * COL_STRIDE);
            const float4 lo = p[0];
            const float4 hi = p[1];
            a[0][j] = lo.x; a[1][j] = lo.y; a[2][j] = lo.z; a[3][j] = lo.w;
            a[4][j] = hi.x; a[5][j] = hi.y; a[6][j] = hi.z; a[7][j] = hi.w;
        }

        // Fully-unrolled in-register LU with partial pivoting
        // (predicated bubble-max swaps; sign tracked via select).
        float det = 1.0f;
        #pragma unroll
        for (int k = 0; k < NB_UP; ++k) {
            #pragma unroll
            for (int r = k + 1; r < NB_UP; ++r) {
                const bool sw = fabsf(a[r][k]) > fabsf(a[k][k]);
                det = sw ? -det : det;
                #pragma unroll
                for (int j = k; j < NB_UP; ++j) {
                    const float t0 = a[k][j];
                    const float t1 = a[r][j];
                    a[k][j] = sw ? t1 : t0;
                    a[r][j] = sw ? t0 : t1;
                }
            }
            const float piv = a[k][k];
            det *= piv;
            const float inv = __frcp_rn(piv);
            #pragma unroll
            for (int r = k + 1; r < NB_UP; ++r) {
                const float f = a[r][k] * inv;
                #pragma unroll
                for (int j = k + 1; j < NB_UP; ++j)
                    a[r][j] = fmaf(-f, a[k][j], a[r][j]);
            }
        }
        result *= det;
    }

    out[(size_t)b * nconf + c] = result;
}

extern "C" void kernel_launch(void* const* d_in, const int* in_sizes, int n_in,
                              void* d_out, int out_size)
{
    const float* mo    = (const float*)d_in[0];  // (B, 16, 40) f32
    const int*   cup   = (const int*)  d_in[1];  // (C, 8) i32
    const int*   cdown = (const int*)  d_in[2];  // (C, 8) i32
    float*       out   = (float*)d_out;          // (B, C) f32

    const int B = in_sizes[0] / (NELEC_ * NMO_);
    const int C = in_sizes[1] / NB_UP;

    slater_det_kernel<<<B, C>>>(mo, cup, cdown, out, C);
}